// round 8
// baseline (speedup 1.0000x reference)
#include <cuda_runtime.h>
#include <cstdint>

#define B_  8
#define C_  128
#define H_  192
#define W_  448
#define ND  49

#define TX  32
#define TY  16
#define KC  16
#define NCHUNK (C_ / KC)
#define NT  224          // 7 warps, one per dj row

#define S1_ROW 36
#define S1_CH  (TY * S1_ROW)        // 576
#define S2_ROW 44                   // col = x + 4, x in [-4, 39]
#define S2_CH  ((TY + 6) * S2_ROW)  // 968
#define S1_SIZE (KC * S1_CH)        // 9216
#define S2_SIZE (KC * S2_CH)        // 15488
#define BUF_SIZE (S1_SIZE + S2_SIZE)               // 24704 floats
#define SMEM_BYTES (2 * BUF_SIZE * sizeof(float))  // 197632 B

typedef unsigned long long ull;

__device__ __forceinline__ uint32_t sptr(const void* p) {
    return (uint32_t)__cvta_generic_to_shared(p);
}
__device__ __forceinline__ void cp16(void* dst, const float* src, bool pred) {
    int bytes = pred ? 16 : 0;
    asm volatile("cp.async.cg.shared.global [%0], [%1], 16, %2;\n"
                 :: "r"(sptr(dst)), "l"(src), "r"(bytes));
}
__device__ __forceinline__ void cp4(void* dst, const float* src, bool pred) {
    int bytes = pred ? 4 : 0;
    asm volatile("cp.async.ca.shared.global [%0], [%1], 4, %2;\n"
                 :: "r"(sptr(dst)), "l"(src), "r"(bytes));
}
__device__ __forceinline__ void cp_commit() {
    asm volatile("cp.async.commit_group;\n" ::: "memory");
}
// 16B shared load as two 64-bit fp32 pairs.
__device__ __forceinline__ void lds2(ull& a, ull& b, uint32_t addr) {
    asm volatile("ld.shared.v2.u64 {%0,%1}, [%2];"
                 : "=l"(a), "=l"(b) : "r"(addr));
}
// packed dual FMA: d.lo += a.lo*b.lo; d.hi += a.hi*b.hi
__device__ __forceinline__ void fma2(ull& d, ull a, ull b) {
    asm("fma.rn.f32x2 %0, %1, %2, %0;" : "+l"(d) : "l"(a), "l"(b));
}
__device__ __forceinline__ void unpack2(float& lo, float& hi, ull v) {
    asm("mov.b64 {%0,%1}, %2;" : "=f"(lo), "=f"(hi) : "l"(v));
}

__device__ __forceinline__ void load_chunk(
    float* __restrict__ s1, float* __restrict__ s2,
    const float* __restrict__ fbase, const float* __restrict__ sbase,
    int c0, int x0, int y0, int tid)
{
    const size_t HW = (size_t)H_ * W_;
    // ---- first tile: 16ch x 16 rows x 8 float4 = 2048 units ----
#pragma unroll
    for (int it = 0; it < 10; ++it) {
        int u = tid + it * NT;
        if (it < 9 || u < 2048) {
            int c = u >> 7;
            int rem = u & 127;
            int row = rem >> 3;
            int q = rem & 7;
            const float* src = fbase + (size_t)(c0 + c) * HW + (size_t)(y0 + row) * W_ + x0 + q * 4;
            cp16(s1 + c * S1_CH + row * S1_ROW + q * 4, src, true);
        }
    }
    // ---- second interior: 16ch x 22 rows x 8 float4 = 2816 units ----
#pragma unroll
    for (int it = 0; it < 13; ++it) {
        int u = tid + it * NT;
        if (it < 12 || u < 2816) {
            int c = u / 176;
            int rem = u - c * 176;
            int row = rem >> 3;
            int q = rem & 7;
            int gy = y0 - 3 + row;
            bool p = (gy >= 0) && (gy < H_);
            int gyc = gy < 0 ? 0 : (gy >= H_ ? H_ - 1 : gy);
            const float* src = sbase + (size_t)(c0 + c) * HW + (size_t)gyc * W_ + x0 + q * 4;
            cp16(s2 + c * S2_CH + row * S2_ROW + 4 + q * 4, src, p);
        }
    }
    // ---- second edges: 16ch x 22 rows x 6 scalars = 2112 units ----
#pragma unroll
    for (int it = 0; it < 10; ++it) {
        int u = tid + it * NT;
        if (it < 9 || u < 2112) {
            int c = u / 132;
            int rem = u - c * 132;
            int row = rem / 6;
            int e = rem - row * 6;
            int x = (e < 3) ? (e - 3) : (TX + e - 3);
            int gy = y0 - 3 + row;
            int gx = x0 + x;
            bool p = (gy >= 0) && (gy < H_) && (gx >= 0) && (gx < W_);
            int gyc = gy < 0 ? 0 : (gy >= H_ ? H_ - 1 : gy);
            int gxc = gx < 0 ? 0 : (gx >= W_ ? W_ - 1 : gx);
            const float* src = sbase + (size_t)(c0 + c) * HW + (size_t)gyc * W_ + gxc;
            cp4(s2 + c * S2_CH + row * S2_ROW + (x + 4), src, p);
        }
    }
}

// Load one channel's f pairs (16 px = 8 pairs) and v pairs (24 floats = 12 even pairs).
__device__ __forceinline__ void load_ch(
    uint32_t a1, uint32_t a2, ull (&e)[12], ull (&fp)[8])
{
    lds2(fp[0], fp[1], a1);
    lds2(fp[2], fp[3], a1 + 16);
    lds2(fp[4], fp[5], a1 + 32);
    lds2(fp[6], fp[7], a1 + 48);
    lds2(e[0],  e[1],  a2);
    lds2(e[2],  e[3],  a2 + 16);
    lds2(e[4],  e[5],  a2 + 32);
    lds2(e[6],  e[7],  a2 + 48);
    lds2(e[8],  e[9],  a2 + 64);
    lds2(e[10], e[11], a2 + 80);
}

// 7 displacements x 16 px = 112 FMA = 56 packed fma2 per channel.
// d odd uses even pairs e[(d+1)/2+pp]; d even uses odd pairs o[d/2+pp],
// where o[k] = (v[2k+1], v[2k+2]).
__device__ __forceinline__ void compute_ch(
    ull* __restrict__ acc2, const ull (&e)[12], const ull (&fp)[8])
{
    ull o[11];
#pragma unroll
    for (int k = 0; k < 11; ++k)
        o[k] = (e[k] >> 32) | (e[k + 1] << 32);
#pragma unroll
    for (int d = 0; d < 7; ++d) {
#pragma unroll
        for (int pp = 0; pp < 8; ++pp) {
            ull vp = (d & 1) ? e[(d + 1) / 2 + pp] : o[d / 2 + pp];
            fma2(acc2[d * 8 + pp], fp[pp], vp);
        }
    }
}

__global__ void __launch_bounds__(NT, 1)
corr_kernel(const float* __restrict__ first,
            const float* __restrict__ second,
            float* __restrict__ out)
{
    extern __shared__ float smem[];
    const int tid = threadIdx.x;
    const int wid = tid >> 5;       // warp = dj row (0..6)
    const int lane = tid & 31;
    const int txl = lane & 1;       // 0..1, owns 16 x-pixels
    const int tyl = lane >> 1;      // 0..15, one y-row
    const int bx = blockIdx.x, by = blockIdx.y, b = blockIdx.z;
    const int x0 = bx * TX, y0 = by * TY;

    const size_t HW = (size_t)H_ * W_;
    const float* fbase = first  + (size_t)b * C_ * HW;
    const float* sbase = second + (size_t)b * C_ * HW;

    const uint32_t smem_base = sptr(smem);
    const uint32_t s1_thr = smem_base + (uint32_t)(tyl * S1_ROW + txl * 16) * 4;
    const uint32_t s2_thr = smem_base + (uint32_t)S1_SIZE * 4
                          + (uint32_t)((tyl + wid) * S2_ROW + txl * 16) * 4;

    ull acc2[56];
#pragma unroll
    for (int i = 0; i < 56; ++i) acc2[i] = 0ull;

    load_chunk(smem, smem + S1_SIZE, fbase, sbase, 0, x0, y0, tid);
    cp_commit();

#pragma unroll 1
    for (int k = 0; k < NCHUNK; ++k) {
        if (k < NCHUNK - 1) {
            float* nb = smem + ((k + 1) & 1) * BUF_SIZE;
            load_chunk(nb, nb + S1_SIZE, fbase, sbase, (k + 1) * KC, x0, y0, tid);
            cp_commit();
            asm volatile("cp.async.wait_group 1;\n" ::: "memory");
        } else {
            asm volatile("cp.async.wait_group 0;\n" ::: "memory");
        }
        __syncthreads();

        const uint32_t boff = (uint32_t)((k & 1) * BUF_SIZE * 4);
        uint32_t a1 = s1_thr + boff;
        uint32_t a2 = s2_thr + boff;

        ull e0[12], f0[8], e1[12], f1[8];
        load_ch(a1, a2, e0, f0);                 // c = 0

#pragma unroll 1
        for (int c = 0; c < KC; c += 2) {
            uint32_t b1 = a1 + S1_CH * 4;
            uint32_t b2 = a2 + S2_CH * 4;
            load_ch(b1, b2, e1, f1);             // c+1
            compute_ch(acc2, e0, f0);            // c
            bool more = (c + 2 < KC);
            uint32_t c1 = more ? b1 + S1_CH * 4 : b1;   // c+2 (dummy reload at tail)
            uint32_t c2 = more ? b2 + S2_CH * 4 : b2;
            load_ch(c1, c2, e0, f0);             // c+2
            compute_ch(acc2, e1, f1);            // c+1
            a1 = c1; a2 = c2;
        }
        __syncthreads();
    }

    // epilogue: mean over channels; warp wid owns flattened d = wid*7 + di
    const float invC = 1.0f / (float)C_;
    const int y = y0 + tyl;
    const int x = x0 + txl * 16;
#pragma unroll
    for (int d = 0; d < 7; ++d) {
        float r[16];
#pragma unroll
        for (int pp = 0; pp < 8; ++pp)
            unpack2(r[pp * 2], r[pp * 2 + 1], acc2[d * 8 + pp]);
        float* op = out + (((size_t)b * ND + wid * 7 + d) * H_ + y) * W_ + x;
#pragma unroll
        for (int q = 0; q < 4; ++q) {
            float4 o;
            o.x = r[q * 4 + 0] * invC;
            o.y = r[q * 4 + 1] * invC;
            o.z = r[q * 4 + 2] * invC;
            o.w = r[q * 4 + 3] * invC;
            ((float4*)op)[q] = o;
        }
    }
}

extern "C" void kernel_launch(void* const* d_in, const int* in_sizes, int n_in,
                              void* d_out, int out_size)
{
    const float* first  = (const float*)d_in[0];
    const float* second = (const float*)d_in[1];
    float* out = (float*)d_out;

    cudaFuncSetAttribute(corr_kernel,
                         cudaFuncAttributeMaxDynamicSharedMemorySize,
                         (int)SMEM_BYTES);

    dim3 grid(W_ / TX, H_ / TY, B_);   // 14 x 12 x 8 = 1344 CTAs
    dim3 block(NT);
    corr_kernel<<<grid, block, SMEM_BYTES>>>(first, second, out);
}